// round 16
// baseline (speedup 1.0000x reference)
#include <cuda_runtime.h>
#include <math.h>
#include <stdint.h>

#define S_LEN   2048
#define HID_DIM 3584
#define NH      28
#define NKV     4
#define NG      7
#define HD      128
#define BM      128
#define BN      64
#define NT      256
#define QT_N    (S_LEN/BM)   // 16

// smem float offsets
#define KS_STRIDE 132
#define VS_STRIDE 136
#define PS_STRIDE 68
#define KS_BUF   (64*KS_STRIDE)          // 8448
#define VS_BUF   (64*VS_STRIDE)          // 8704
#define SM_K     0
#define SM_V     (2*KS_BUF)              // 16896
#define SM_P     (SM_V + 2*VS_BUF)       // 34304
#define SM_TOT   (SM_P + 128*PS_STRIDE)  // 43008 floats = 172032 B

// tf32-rounded scratch, layout [head][seq][dim]
__device__ float g_Q[(size_t)NH  * S_LEN * HD];
__device__ float g_K[(size_t)NKV * S_LEN * HD];
__device__ float g_V[(size_t)NKV * S_LEN * HD];

__device__ __forceinline__ float ex2(float x) {
    float y; asm("ex2.approx.ftz.f32 %0, %1;" : "=f"(y) : "f"(x)); return y;
}
__device__ __forceinline__ float tf32r(float x) {
    uint32_t y; asm("cvt.rna.tf32.f32 %0, %1;" : "=r"(y) : "f"(x));
    return __uint_as_float(y);
}
__device__ __forceinline__ uint32_t s2u(const void* p) {
    uint32_t a;
    asm("{ .reg .u64 t; cvta.to.shared.u64 t, %1; cvt.u32.u64 %0, t; }"
        : "=r"(a) : "l"(p));
    return a;
}
__device__ __forceinline__ void cp16(uint32_t dst, const void* src) {
    asm volatile("cp.async.cg.shared.global [%0], [%1], 16;" :: "r"(dst), "l"(src));
}
__device__ __forceinline__ void cp_commit() { asm volatile("cp.async.commit_group;"); }
__device__ __forceinline__ void cp_wait0()  { asm volatile("cp.async.wait_group 0;" ::: "memory"); }

__device__ __forceinline__ void mma8(float* c, uint32_t a0, uint32_t a1,
                                     uint32_t a2, uint32_t a3,
                                     uint32_t b0, uint32_t b1) {
    asm("mma.sync.aligned.m16n8k8.row.col.f32.tf32.tf32.f32 "
        "{%0,%1,%2,%3},{%4,%5,%6,%7},{%8,%9},{%0,%1,%2,%3};"
        : "+f"(c[0]), "+f"(c[1]), "+f"(c[2]), "+f"(c[3])
        : "r"(a0), "r"(a1), "r"(a2), "r"(a3), "r"(b0), "r"(b1));
}

// ---------------------------------------------------------------------------
__global__ void rope_kernel(const float* __restrict__ x,
                            const float* __restrict__ cosb,
                            const float* __restrict__ sinb,
                            int nheads, int row_stride, float scale, int which) {
    int idx = blockIdx.x * blockDim.x + threadIdx.x;
    if (idx >= S_LEN * nheads * 64) return;
    int d = idx & 63, h = (idx >> 6) % nheads, s = idx / (64 * nheads);
    const float* xr = x + (size_t)s * row_stride + h * HD;
    float x1 = xr[d], x2 = xr[d + 64];
    float o1 = (x1 * cosb[s*HD+d]    - x2 * sinb[s*HD+d])    * scale;
    float o2 = (x2 * cosb[s*HD+d+64] + x1 * sinb[s*HD+d+64]) * scale;
    float* orow = (which ? g_K : g_Q) + ((size_t)h * S_LEN + s) * HD;
    orow[d]      = tf32r(o1);
    orow[d + 64] = tf32r(o2);
}

__global__ void vconv_kernel(const float* __restrict__ v) {
    int idx = blockIdx.x * blockDim.x + threadIdx.x;
    if (idx >= NKV * S_LEN * HD) return;
    int d = idx & 127, kh = (idx >> 7) & 3, s = idx >> 9;
    g_V[((size_t)kh * S_LEN + s) * HD + d] = tf32r(v[idx]);
}

// ---------------------------------------------------------------------------
// tf32 mma.sync flash attention, v2:
//  - Q fragments held in registers (loaded once)
//  - K/V double-buffered, one cp.async group per tile, prefetch 1 tile ahead
//  - ONE __syncthreads per tile (P is warp-private -> __syncwarp only)
// ---------------------------------------------------------------------------
__global__ __launch_bounds__(NT, 1)
void attn_mma(float* __restrict__ out) {
    extern __shared__ float sm[];
    float* Ks = sm + SM_K;
    float* Vs = sm + SM_V;
    float* Ps = sm + SM_P;

    const int tid = threadIdx.x, lane = tid & 31, w = tid >> 5;
    const int qt = (QT_N - 1) - (int)(blockIdx.x & 15);
    const int h  = (int)(blockIdx.x >> 4), kh = h / NG;
    const int m0 = qt * BM, R = 16 * w;
    const int r0 = lane >> 2, cq = lane & 3;
    const int nt = 2 * qt + 2;

    const float* Kg = g_K + (size_t)kh * S_LEN * HD;
    const float* Vg = g_V + (size_t)kh * S_LEN * HD;
    const uint32_t ks_u = s2u(Ks), vs_u = s2u(Vs);

    // Q fragments -> registers (one-time gmem gather)
    float qf[16][4];
    {
        const float* Qg = g_Q + ((size_t)h * S_LEN + m0 + R) * HD;
        #pragma unroll
        for (int kk = 0; kk < 16; kk++) {
            qf[kk][0] = Qg[(size_t)r0       * HD + kk * 8 + cq];
            qf[kk][1] = Qg[(size_t)(r0 + 8) * HD + kk * 8 + cq];
            qf[kk][2] = Qg[(size_t)r0       * HD + kk * 8 + cq + 4];
            qf[kk][3] = Qg[(size_t)(r0 + 8) * HD + kk * 8 + cq + 4];
        }
    }

    // Prologue: group 0 = K(0)+V(0) into buffer 0
    #pragma unroll
    for (int i = 0; i < 8; i++) {
        int id = tid + NT * i, row = id >> 5, c = id & 31;
        cp16(ks_u + (row * KS_STRIDE + c * 4) * 4, Kg + (size_t)row * HD + c * 4);
    }
    #pragma unroll
    for (int i = 0; i < 8; i++) {
        int id = tid + NT * i, row = id >> 5, c = id & 31;
        cp16(vs_u + (row * VS_STRIDE + c * 4) * 4, Vg + (size_t)row * HD + c * 4);
    }
    cp_commit();

    const float NEG_INF = __int_as_float(0xff800000);
    float m0f = NEG_INF, m1f = NEG_INF, l0 = 0.f, l1 = 0.f;
    float o[16][4];
    #pragma unroll
    for (int jn = 0; jn < 16; jn++)
        #pragma unroll
        for (int e = 0; e < 4; e++) o[jn][e] = 0.f;

    for (int t = 0; t < nt; t++) {
        const int n0 = t * BN;
        const int buf = t & 1;
        const int kb = buf ? KS_BUF : 0, vb = buf ? VS_BUF : 0;
        const int kbn = buf ? 0 : KS_BUF, vbn = buf ? 0 : VS_BUF;

        cp_wait0();            // tile t data arrived
        __syncthreads();       // ...visible to all; prior reads of alt buf done

        if (t + 1 < nt) {      // prefetch tile t+1 into the other buffer
            #pragma unroll
            for (int i = 0; i < 8; i++) {
                int id = tid + NT * i, row = id >> 5, c = id & 31;
                cp16(ks_u + (kbn + row * KS_STRIDE + c * 4) * 4,
                     Kg + (size_t)(n0 + BN + row) * HD + c * 4);
            }
            #pragma unroll
            for (int i = 0; i < 8; i++) {
                int id = tid + NT * i, row = id >> 5, c = id & 31;
                cp16(vs_u + (vbn + row * VS_STRIDE + c * 4) * 4,
                     Vg + (size_t)(n0 + BN + row) * HD + c * 4);
            }
            cp_commit();
        }

        // ---- S = Q K^T ----
        float s[8][4];
        #pragma unroll
        for (int j = 0; j < 8; j++)
            #pragma unroll
            for (int e = 0; e < 4; e++) s[j][e] = 0.f;
        #pragma unroll 4
        for (int kk = 0; kk < 16; kk++) {
            uint32_t a0 = __float_as_uint(qf[kk][0]);
            uint32_t a1 = __float_as_uint(qf[kk][1]);
            uint32_t a2 = __float_as_uint(qf[kk][2]);
            uint32_t a3 = __float_as_uint(qf[kk][3]);
            #pragma unroll
            for (int j = 0; j < 8; j++) {
                int koff = kb + (j * 8 + r0) * KS_STRIDE + kk * 8 + cq;
                mma8(s[j], a0, a1, a2, a3,
                     __float_as_uint(Ks[koff]), __float_as_uint(Ks[koff + 4]));
            }
        }

        // ---- mask (last 2 tiles) + online softmax (quad shuffles) ----
        const int row0 = m0 + R + r0, row1 = row0 + 8;
        if (t >= nt - 2) {
            #pragma unroll
            for (int j = 0; j < 8; j++) {
                int c0 = n0 + 8 * j + 2 * cq;
                if (c0     > row0) s[j][0] = NEG_INF;
                if (c0 + 1 > row0) s[j][1] = NEG_INF;
                if (c0     > row1) s[j][2] = NEG_INF;
                if (c0 + 1 > row1) s[j][3] = NEG_INF;
            }
        }
        float mx0 = NEG_INF, mx1 = NEG_INF;
        #pragma unroll
        for (int j = 0; j < 8; j++) {
            mx0 = fmaxf(mx0, fmaxf(s[j][0], s[j][1]));
            mx1 = fmaxf(mx1, fmaxf(s[j][2], s[j][3]));
        }
        mx0 = fmaxf(mx0, __shfl_xor_sync(0xffffffffu, mx0, 1));
        mx0 = fmaxf(mx0, __shfl_xor_sync(0xffffffffu, mx0, 2));
        mx1 = fmaxf(mx1, __shfl_xor_sync(0xffffffffu, mx1, 1));
        mx1 = fmaxf(mx1, __shfl_xor_sync(0xffffffffu, mx1, 2));
        float nm0 = fmaxf(m0f, mx0), nm1 = fmaxf(m1f, mx1);
        float sc0 = ex2(m0f - nm0), sc1 = ex2(m1f - nm1);
        m0f = nm0; m1f = nm1;
        float sum0 = 0.f, sum1 = 0.f;
        #pragma unroll
        for (int j = 0; j < 8; j++) {
            s[j][0] = ex2(s[j][0] - nm0); s[j][1] = ex2(s[j][1] - nm0);
            s[j][2] = ex2(s[j][2] - nm1); s[j][3] = ex2(s[j][3] - nm1);
            sum0 += s[j][0] + s[j][1];
            sum1 += s[j][2] + s[j][3];
        }
        sum0 += __shfl_xor_sync(0xffffffffu, sum0, 1);
        sum0 += __shfl_xor_sync(0xffffffffu, sum0, 2);
        sum1 += __shfl_xor_sync(0xffffffffu, sum1, 1);
        sum1 += __shfl_xor_sync(0xffffffffu, sum1, 2);
        l0 = l0 * sc0 + sum0;
        l1 = l1 * sc1 + sum1;
        #pragma unroll
        for (int jn = 0; jn < 16; jn++) {
            o[jn][0] *= sc0; o[jn][1] *= sc0;
            o[jn][2] *= sc1; o[jn][3] *= sc1;
        }
        // P write (warp-private rows; tf32-rounded)
        #pragma unroll
        for (int j = 0; j < 8; j++) {
            *(float2*)&Ps[(R + r0)     * PS_STRIDE + 8 * j + 2 * cq] =
                make_float2(tf32r(s[j][0]), tf32r(s[j][1]));
            *(float2*)&Ps[(R + r0 + 8) * PS_STRIDE + 8 * j + 2 * cq] =
                make_float2(tf32r(s[j][2]), tf32r(s[j][3]));
        }
        __syncwarp();

        // ---- O += P V ----
        #pragma unroll 2
        for (int kk = 0; kk < 8; kk++) {
            int poff = (R + r0) * PS_STRIDE + kk * 8 + cq;
            uint32_t a0 = __float_as_uint(Ps[poff]);
            uint32_t a1 = __float_as_uint(Ps[poff + 8 * PS_STRIDE]);
            uint32_t a2 = __float_as_uint(Ps[poff + 4]);
            uint32_t a3 = __float_as_uint(Ps[poff + 8 * PS_STRIDE + 4]);
            #pragma unroll
            for (int jn = 0; jn < 16; jn++) {
                int voff = vb + (kk * 8 + cq) * VS_STRIDE + jn * 8 + r0;
                mma8(o[jn], a0, a1, a2, a3,
                     __float_as_uint(Vs[voff]),
                     __float_as_uint(Vs[voff + 4 * VS_STRIDE]));
            }
        }
    }

    // ---- epilogue ----
    float inv0 = 1.0f / l0, inv1 = 1.0f / l1;
    float* op0 = out + (size_t)(m0 + R + r0)     * HID_DIM + h * HD;
    float* op1 = out + (size_t)(m0 + R + r0 + 8) * HID_DIM + h * HD;
    #pragma unroll
    for (int jn = 0; jn < 16; jn++) {
        *(float2*)&op0[8 * jn + 2 * cq] = make_float2(o[jn][0] * inv0, o[jn][1] * inv0);
        *(float2*)&op1[8 * jn + 2 * cq] = make_float2(o[jn][2] * inv1, o[jn][3] * inv1);
    }
}

// ---------------------------------------------------------------------------
extern "C" void kernel_launch(void* const* d_in, const int* in_sizes, int n_in,
                              void* d_out, int out_size) {
    (void)in_sizes; (void)n_in; (void)out_size;
    const float* q    = (const float*)d_in[0];
    const float* k    = (const float*)d_in[1];
    const float* v    = (const float*)d_in[2];
    const float* cosb = (const float*)d_in[3];
    const float* sinb = (const float*)d_in[4];
    float* out = (float*)d_out;

    const float qscale = 1.4426950408889634f / sqrtf((float)HD);
    int totq = S_LEN * NH * 64, totk = S_LEN * NKV * 64;
    rope_kernel<<<(totq + 255) / 256, 256>>>(q, cosb, sinb, NH, HID_DIM, qscale, 0);
    rope_kernel<<<(totk + 255) / 256, 256>>>(k, cosb, sinb, NKV, NKV * HD, 1.0f, 1);
    vconv_kernel<<<(NKV * S_LEN * HD + 255) / 256, 256>>>(v);

    const int smem_bytes = SM_TOT * 4;   // 172032
    cudaFuncSetAttribute(attn_mma,
                         cudaFuncAttributeMaxDynamicSharedMemorySize, smem_bytes);
    attn_mma<<<NH * QT_N, NT, smem_bytes>>>(out);
}